// round 1
// baseline (speedup 1.0000x reference)
#include <cuda_runtime.h>
#include <cuda_bf16.h>

#define K_NB   10
#define K_TOT  300
#define ESTRIDE 20   // floats per smem ctrl entry (19 used + 1 pad)
#define TPB    256

// smem entry layout (per control point j):
//  [0..8]  R row-major
//  [9..11] ctrl position p
//  [12..14] p + translation
//  [15..18] ctrl quaternion (w,x,y,z), normalized

__global__ __launch_bounds__(TPB)
void deform4d_kernel(const float* __restrict__ means,
                     const float* __restrict__ quats,
                     const float* __restrict__ weights,
                     const float* __restrict__ ctrl_trans,
                     const float* __restrict__ ctrl_rots,
                     const float* __restrict__ ctrl_pos,
                     const int*   __restrict__ indices,
                     float* __restrict__ out_means,
                     float* __restrict__ out_quats,
                     int n)
{
    __shared__ float s[K_TOT * ESTRIDE];

    // ---- cooperative precompute of control-point transforms ----
    for (int j = threadIdx.x; j < K_TOT; j += TPB) {
        float qw = ctrl_rots[j * 4 + 0];
        float qx = ctrl_rots[j * 4 + 1];
        float qy = ctrl_rots[j * 4 + 2];
        float qz = ctrl_rots[j * 4 + 3];
        float nrm = sqrtf(qw * qw + qx * qx + qy * qy + qz * qz);
        float inv = 1.0f / fmaxf(nrm, 1e-8f);
        qw *= inv; qx *= inv; qy *= inv; qz *= inv;

        float* e = s + j * ESTRIDE;
        e[0] = 1.f - 2.f * (qy * qy + qz * qz);
        e[1] = 2.f * (qx * qy - qw * qz);
        e[2] = 2.f * (qx * qz + qw * qy);
        e[3] = 2.f * (qx * qy + qw * qz);
        e[4] = 1.f - 2.f * (qx * qx + qz * qz);
        e[5] = 2.f * (qy * qz - qw * qx);
        e[6] = 2.f * (qx * qz - qw * qy);
        e[7] = 2.f * (qy * qz + qw * qx);
        e[8] = 1.f - 2.f * (qx * qx + qy * qy);

        float px = ctrl_pos[j * 3 + 0];
        float py = ctrl_pos[j * 3 + 1];
        float pz = ctrl_pos[j * 3 + 2];
        e[9]  = px; e[10] = py; e[11] = pz;
        e[12] = px + ctrl_trans[j * 3 + 0];
        e[13] = py + ctrl_trans[j * 3 + 1];
        e[14] = pz + ctrl_trans[j * 3 + 2];
        e[15] = qw; e[16] = qx; e[17] = qy; e[18] = qz;
        e[19] = 0.f;
    }
    __syncthreads();

    int i = blockIdx.x * TPB + threadIdx.x;
    if (i >= n) return;

    // ---- per-gaussian loads ----
    float mx = means[i * 3 + 0];
    float my = means[i * 3 + 1];
    float mz = means[i * 3 + 2];

    float4 gq = reinterpret_cast<const float4*>(quats)[i];  // (w,x,y,z)

    // weights: 10 floats at 40B stride -> 5x float2 (8B aligned)
    float wv[K_NB];
    {
        const float2* wp = reinterpret_cast<const float2*>(weights + (size_t)i * K_NB);
        #pragma unroll
        for (int k = 0; k < 5; k++) {
            float2 t = wp[k];
            wv[2 * k + 0] = t.x;
            wv[2 * k + 1] = t.y;
        }
    }
    int jv[K_NB];
    {
        const int2* ip = reinterpret_cast<const int2*>(indices + (size_t)i * K_NB);
        #pragma unroll
        for (int k = 0; k < 5; k++) {
            int2 t = ip[k];
            jv[2 * k + 0] = t.x;
            jv[2 * k + 1] = t.y;
        }
    }

    // ---- blend ----
    float am0 = 0.f, am1 = 0.f, am2 = 0.f;
    float aq0 = 0.f, aq1 = 0.f, aq2 = 0.f, aq3 = 0.f;

    #pragma unroll
    for (int k = 0; k < K_NB; k++) {
        const float w = wv[k];
        const float* e = s + jv[k] * ESTRIDE;

        float dx = mx - e[9];
        float dy = my - e[10];
        float dz = mz - e[11];

        float rx = e[0] * dx + e[1] * dy + e[2] * dz;
        float ry = e[3] * dx + e[4] * dy + e[5] * dz;
        float rz = e[6] * dx + e[7] * dy + e[8] * dz;

        am0 = fmaf(w, rx + e[12], am0);
        am1 = fmaf(w, ry + e[13], am1);
        am2 = fmaf(w, rz + e[14], am2);

        aq0 = fmaf(w, e[15], aq0);
        aq1 = fmaf(w, e[16], aq1);
        aq2 = fmaf(w, e[17], aq2);
        aq3 = fmaf(w, e[18], aq3);
    }

    // normalize blended quaternion (matches reference eps handling)
    float nrm = sqrtf(aq0 * aq0 + aq1 * aq1 + aq2 * aq2 + aq3 * aq3);
    float inv = 1.0f / fmaxf(nrm, 1e-8f);
    float aw = aq0 * inv, ax = aq1 * inv, ay = aq2 * inv, az = aq3 * inv;

    // Hamilton product: blended * gaussian quat
    float bw = gq.x, bx = gq.y, by = gq.z, bz = gq.w;
    float4 qo;
    qo.x = aw * bw - ax * bx - ay * by - az * bz;
    qo.y = aw * bx + ax * bw + ay * bz - az * by;
    qo.z = aw * by - ax * bz + ay * bw + az * bx;
    qo.w = aw * bz + ax * by - ay * bx + az * bw;

    out_means[i * 3 + 0] = am0;
    out_means[i * 3 + 1] = am1;
    out_means[i * 3 + 2] = am2;
    reinterpret_cast<float4*>(out_quats)[i] = qo;
}

extern "C" void kernel_launch(void* const* d_in, const int* in_sizes, int n_in,
                              void* d_out, int out_size)
{
    const float* means      = (const float*)d_in[0];
    const float* quats      = (const float*)d_in[1];
    const float* weights    = (const float*)d_in[2];
    const float* ctrl_trans = (const float*)d_in[3];
    const float* ctrl_rots  = (const float*)d_in[4];
    const float* ctrl_pos   = (const float*)d_in[5];
    const int*   indices    = (const int*)d_in[6];

    int n = in_sizes[0] / 3;  // means is [N,3]

    float* out_means = (float*)d_out;
    float* out_quats = (float*)d_out + (size_t)n * 3;

    int blocks = (n + TPB - 1) / TPB;
    deform4d_kernel<<<blocks, TPB>>>(means, quats, weights,
                                     ctrl_trans, ctrl_rots, ctrl_pos,
                                     indices, out_means, out_quats, n);
}

// round 2
// speedup vs baseline: 1.1383x; 1.1383x over previous
#include <cuda_runtime.h>
#include <cuda_bf16.h>

#define K_NB    10
#define K_TOT   300
#define EV      5      // float4s per smem ctrl entry (4 used + 1 pad => 80B stride)
#define TPB     256

// smem entry layout (per control point j), as float4:
//  [0] = {R00, R01, R02, b0}
//  [1] = {R10, R11, R12, b1}
//  [2] = {R20, R21, R22, b2}   where b = p + t - R*p
//  [3] = {qw, qx, qy, qz}      normalized ctrl quaternion
//  [4] = pad (bank-conflict spreading)

__global__ __launch_bounds__(TPB)
void deform4d_kernel(const float* __restrict__ means,
                     const float* __restrict__ quats,
                     const float* __restrict__ weights,
                     const float* __restrict__ ctrl_trans,
                     const float* __restrict__ ctrl_rots,
                     const float* __restrict__ ctrl_pos,
                     const int*   __restrict__ indices,
                     float* __restrict__ out_means,
                     float* __restrict__ out_quats,
                     int n)
{
    __shared__ float4 s4[K_TOT * EV];

    const int i = blockIdx.x * TPB + threadIdx.x;
    const bool active = (i < n);

    // ---- issue all per-gaussian global loads up front (overlap with table build) ----
    float mx = 0.f, my = 0.f, mz = 0.f;
    float4 gq = make_float4(0.f, 0.f, 0.f, 0.f);
    float wv[K_NB];
    int   jv[K_NB];
    if (active) {
        mx = means[i * 3 + 0];
        my = means[i * 3 + 1];
        mz = means[i * 3 + 2];
        gq = reinterpret_cast<const float4*>(quats)[i];   // (w,x,y,z)
        const float2* wp = reinterpret_cast<const float2*>(weights + (size_t)i * K_NB);
        const int2*   ip = reinterpret_cast<const int2*>(indices + (size_t)i * K_NB);
        #pragma unroll
        for (int k = 0; k < 5; k++) {
            float2 tw = wp[k];
            int2   ti = ip[k];
            wv[2 * k + 0] = tw.x;  wv[2 * k + 1] = tw.y;
            jv[2 * k + 0] = ti.x;  jv[2 * k + 1] = ti.y;
        }
    } else {
        #pragma unroll
        for (int k = 0; k < K_NB; k++) { wv[k] = 0.f; jv[k] = 0; }
    }

    // ---- cooperative precompute of control-point transforms ----
    for (int j = threadIdx.x; j < K_TOT; j += TPB) {
        float4 q = reinterpret_cast<const float4*>(ctrl_rots)[j];
        float nrm = sqrtf(q.x * q.x + q.y * q.y + q.z * q.z + q.w * q.w);
        float inv = 1.0f / fmaxf(nrm, 1e-8f);
        float qw = q.x * inv, qx = q.y * inv, qy = q.z * inv, qz = q.w * inv;

        float R00 = 1.f - 2.f * (qy * qy + qz * qz);
        float R01 = 2.f * (qx * qy - qw * qz);
        float R02 = 2.f * (qx * qz + qw * qy);
        float R10 = 2.f * (qx * qy + qw * qz);
        float R11 = 1.f - 2.f * (qx * qx + qz * qz);
        float R12 = 2.f * (qy * qz - qw * qx);
        float R20 = 2.f * (qx * qz - qw * qy);
        float R21 = 2.f * (qy * qz + qw * qx);
        float R22 = 1.f - 2.f * (qx * qx + qy * qy);

        float px = ctrl_pos[j * 3 + 0];
        float py = ctrl_pos[j * 3 + 1];
        float pz = ctrl_pos[j * 3 + 2];
        float b0 = px + ctrl_trans[j * 3 + 0] - (R00 * px + R01 * py + R02 * pz);
        float b1 = py + ctrl_trans[j * 3 + 1] - (R10 * px + R11 * py + R12 * pz);
        float b2 = pz + ctrl_trans[j * 3 + 2] - (R20 * px + R21 * py + R22 * pz);

        float4* e = s4 + j * EV;
        e[0] = make_float4(R00, R01, R02, b0);
        e[1] = make_float4(R10, R11, R12, b1);
        e[2] = make_float4(R20, R21, R22, b2);
        e[3] = make_float4(qw, qx, qy, qz);
    }
    __syncthreads();

    if (!active) return;

    // ---- blend ----
    float am0 = 0.f, am1 = 0.f, am2 = 0.f;
    float aq0 = 0.f, aq1 = 0.f, aq2 = 0.f, aq3 = 0.f;

    #pragma unroll
    for (int k = 0; k < K_NB; k++) {
        const float   w = wv[k];
        const float4* e = s4 + jv[k] * EV;
        float4 r0 = e[0];
        float4 r1 = e[1];
        float4 r2 = e[2];
        float4 cq = e[3];

        float rx = fmaf(r0.x, mx, fmaf(r0.y, my, fmaf(r0.z, mz, r0.w)));
        float ry = fmaf(r1.x, mx, fmaf(r1.y, my, fmaf(r1.z, mz, r1.w)));
        float rz = fmaf(r2.x, mx, fmaf(r2.y, my, fmaf(r2.z, mz, r2.w)));

        am0 = fmaf(w, rx, am0);
        am1 = fmaf(w, ry, am1);
        am2 = fmaf(w, rz, am2);

        aq0 = fmaf(w, cq.x, aq0);
        aq1 = fmaf(w, cq.y, aq1);
        aq2 = fmaf(w, cq.z, aq2);
        aq3 = fmaf(w, cq.w, aq3);
    }

    // normalize blended quaternion (matches reference eps handling)
    float nrm = sqrtf(aq0 * aq0 + aq1 * aq1 + aq2 * aq2 + aq3 * aq3);
    float inv = 1.0f / fmaxf(nrm, 1e-8f);
    float aw = aq0 * inv, ax = aq1 * inv, ay = aq2 * inv, az = aq3 * inv;

    // Hamilton product: blended * gaussian quat  (w,x,y,z)
    float bw = gq.x, bx = gq.y, by = gq.z, bz = gq.w;
    float4 qo;
    qo.x = aw * bw - ax * bx - ay * by - az * bz;
    qo.y = aw * bx + ax * bw + ay * bz - az * by;
    qo.z = aw * by - ax * bz + ay * bw + az * bx;
    qo.w = aw * bz + ax * by - ay * bx + az * bw;

    out_means[i * 3 + 0] = am0;
    out_means[i * 3 + 1] = am1;
    out_means[i * 3 + 2] = am2;
    reinterpret_cast<float4*>(out_quats)[i] = qo;
}

extern "C" void kernel_launch(void* const* d_in, const int* in_sizes, int n_in,
                              void* d_out, int out_size)
{
    const float* means      = (const float*)d_in[0];
    const float* quats      = (const float*)d_in[1];
    const float* weights    = (const float*)d_in[2];
    const float* ctrl_trans = (const float*)d_in[3];
    const float* ctrl_rots  = (const float*)d_in[4];
    const float* ctrl_pos   = (const float*)d_in[5];
    const int*   indices    = (const int*)d_in[6];

    int n = in_sizes[0] / 3;  // means is [N,3]

    float* out_means = (float*)d_out;
    float* out_quats = (float*)d_out + (size_t)n * 3;

    int blocks = (n + TPB - 1) / TPB;
    deform4d_kernel<<<blocks, TPB>>>(means, quats, weights,
                                     ctrl_trans, ctrl_rots, ctrl_pos,
                                     indices, out_means, out_quats, n);
}

// round 3
// speedup vs baseline: 1.5903x; 1.3970x over previous
#include <cuda_runtime.h>
#include <cuda_bf16.h>

#define K_NB    10
#define K_TOT   300
#define EV      3      // float4s per smem ctrl entry (2 used + 1 pad => 48B stride, coprime w/ bank period)
#define TPB     256

// smem entry layout (per control point j), as float4:
//  [0] = {qw, qx, qy, qz}   normalized ctrl quaternion
//  [1] = {b0, b1, b2, 0}    where b = p + t - rot_q(p)
//  [2] = pad (bank spreading: stride 3*16B cycles all 8 quad-bank positions)

__device__ __forceinline__ void quat_rotate(float cw, float cx, float cy, float cz,
                                            float vx, float vy, float vz,
                                            float& ox, float& oy, float& oz)
{
    // t = qv x v
    float tx = cy * vz - cz * vy;
    float ty = cz * vx - cx * vz;
    float tz = cx * vy - cy * vx;
    // u = qv x t
    float ux = cy * tz - cz * ty;
    float uy = cz * tx - cx * tz;
    float uz = cx * ty - cy * tx;
    // v' = v + 2*(w*t + u)
    ox = fmaf(2.f, fmaf(cw, tx, ux), vx);
    oy = fmaf(2.f, fmaf(cw, ty, uy), vy);
    oz = fmaf(2.f, fmaf(cw, tz, uz), vz);
}

__global__ __launch_bounds__(TPB)
void deform4d_kernel(const float* __restrict__ means,
                     const float* __restrict__ quats,
                     const float* __restrict__ weights,
                     const float* __restrict__ ctrl_trans,
                     const float* __restrict__ ctrl_rots,
                     const float* __restrict__ ctrl_pos,
                     const int*   __restrict__ indices,
                     float* __restrict__ out_means,
                     float* __restrict__ out_quats,
                     int n)
{
    __shared__ float4 s4[K_TOT * EV];

    const int i = blockIdx.x * TPB + threadIdx.x;
    const bool active = (i < n);

    // ---- issue all per-gaussian global loads up front (overlap with table build) ----
    float mx = 0.f, my = 0.f, mz = 0.f;
    float4 gq = make_float4(0.f, 0.f, 0.f, 0.f);
    float wv[K_NB];
    int   jv[K_NB];
    if (active) {
        mx = means[i * 3 + 0];
        my = means[i * 3 + 1];
        mz = means[i * 3 + 2];
        gq = reinterpret_cast<const float4*>(quats)[i];   // (w,x,y,z)
        const float2* wp = reinterpret_cast<const float2*>(weights + (size_t)i * K_NB);
        const int2*   ip = reinterpret_cast<const int2*>(indices + (size_t)i * K_NB);
        #pragma unroll
        for (int k = 0; k < 5; k++) {
            float2 tw = wp[k];
            int2   ti = ip[k];
            wv[2 * k + 0] = tw.x;  wv[2 * k + 1] = tw.y;
            jv[2 * k + 0] = ti.x;  jv[2 * k + 1] = ti.y;
        }
    } else {
        #pragma unroll
        for (int k = 0; k < K_NB; k++) { wv[k] = 0.f; jv[k] = 0; }
    }

    // ---- cooperative precompute of control-point transforms ----
    for (int j = threadIdx.x; j < K_TOT; j += TPB) {
        float4 q = reinterpret_cast<const float4*>(ctrl_rots)[j];
        float nrm = sqrtf(q.x * q.x + q.y * q.y + q.z * q.z + q.w * q.w);
        float inv = 1.0f / fmaxf(nrm, 1e-8f);
        float cw = q.x * inv, cx = q.y * inv, cy = q.z * inv, cz = q.w * inv;

        float px = ctrl_pos[j * 3 + 0];
        float py = ctrl_pos[j * 3 + 1];
        float pz = ctrl_pos[j * 3 + 2];

        float rpx, rpy, rpz;
        quat_rotate(cw, cx, cy, cz, px, py, pz, rpx, rpy, rpz);

        float b0 = px + ctrl_trans[j * 3 + 0] - rpx;
        float b1 = py + ctrl_trans[j * 3 + 1] - rpy;
        float b2 = pz + ctrl_trans[j * 3 + 2] - rpz;

        float4* e = s4 + j * EV;
        e[0] = make_float4(cw, cx, cy, cz);
        e[1] = make_float4(b0, b1, b2, 0.f);
    }
    __syncthreads();

    if (!active) return;

    // ---- blend ----
    float am0 = 0.f, am1 = 0.f, am2 = 0.f;
    float aq0 = 0.f, aq1 = 0.f, aq2 = 0.f, aq3 = 0.f;

    #pragma unroll
    for (int k = 0; k < K_NB; k++) {
        const float   w = wv[k];
        const float4* e = s4 + jv[k] * EV;
        float4 cq = e[0];
        float4 b  = e[1];

        float vx, vy, vz;
        quat_rotate(cq.x, cq.y, cq.z, cq.w, mx, my, mz, vx, vy, vz);

        am0 = fmaf(w, vx + b.x, am0);
        am1 = fmaf(w, vy + b.y, am1);
        am2 = fmaf(w, vz + b.z, am2);

        aq0 = fmaf(w, cq.x, aq0);
        aq1 = fmaf(w, cq.y, aq1);
        aq2 = fmaf(w, cq.z, aq2);
        aq3 = fmaf(w, cq.w, aq3);
    }

    // normalize blended quaternion (matches reference eps handling)
    float nrm = sqrtf(aq0 * aq0 + aq1 * aq1 + aq2 * aq2 + aq3 * aq3);
    float inv = 1.0f / fmaxf(nrm, 1e-8f);
    float aw = aq0 * inv, ax = aq1 * inv, ay = aq2 * inv, az = aq3 * inv;

    // Hamilton product: blended * gaussian quat  (w,x,y,z)
    float bw = gq.x, bx = gq.y, by = gq.z, bz = gq.w;
    float4 qo;
    qo.x = aw * bw - ax * bx - ay * by - az * bz;
    qo.y = aw * bx + ax * bw + ay * bz - az * by;
    qo.z = aw * by - ax * bz + ay * bw + az * bx;
    qo.w = aw * bz + ax * by - ay * bx + az * bw;

    out_means[i * 3 + 0] = am0;
    out_means[i * 3 + 1] = am1;
    out_means[i * 3 + 2] = am2;
    reinterpret_cast<float4*>(out_quats)[i] = qo;
}

extern "C" void kernel_launch(void* const* d_in, const int* in_sizes, int n_in,
                              void* d_out, int out_size)
{
    const float* means      = (const float*)d_in[0];
    const float* quats      = (const float*)d_in[1];
    const float* weights    = (const float*)d_in[2];
    const float* ctrl_trans = (const float*)d_in[3];
    const float* ctrl_rots  = (const float*)d_in[4];
    const float* ctrl_pos   = (const float*)d_in[5];
    const int*   indices    = (const int*)d_in[6];

    int n = in_sizes[0] / 3;  // means is [N,3]

    float* out_means = (float*)d_out;
    float* out_quats = (float*)d_out + (size_t)n * 3;

    int blocks = (n + TPB - 1) / TPB;
    deform4d_kernel<<<blocks, TPB>>>(means, quats, weights,
                                     ctrl_trans, ctrl_rots, ctrl_pos,
                                     indices, out_means, out_quats, n);
}

// round 4
// speedup vs baseline: 1.8383x; 1.1560x over previous
#include <cuda_runtime.h>
#include <cuda_bf16.h>

#define K_NB    10
#define K_TOT   300
#define EV      3      // float4s per smem ctrl entry (2 used + 1 pad => 48B stride, coprime w/ 8 quad-bank period)
#define TPB     256
#define BLKS_PER_SM 5
#define NUM_SMS 148

// smem entry layout (per control point j), as float4:
//  [0] = {qw, qx, qy, qz}   normalized ctrl quaternion
//  [1] = {b0, b1, b2, 0}    where b = p + t - rot_q(p)
//  [2] = pad (bank spreading)

__device__ __forceinline__ void quat_rotate(float cw, float cx, float cy, float cz,
                                            float vx, float vy, float vz,
                                            float& ox, float& oy, float& oz)
{
    float tx = cy * vz - cz * vy;
    float ty = cz * vx - cx * vz;
    float tz = cx * vy - cy * vx;
    float ux = cy * tz - cz * ty;
    float uy = cz * tx - cx * tz;
    float uz = cx * ty - cy * tx;
    ox = fmaf(2.f, fmaf(cw, tx, ux), vx);
    oy = fmaf(2.f, fmaf(cw, ty, uy), vy);
    oz = fmaf(2.f, fmaf(cw, tz, uz), vz);
}

__global__ __launch_bounds__(TPB, BLKS_PER_SM)
void deform4d_kernel(const float* __restrict__ means,
                     const float* __restrict__ quats,
                     const float* __restrict__ weights,
                     const float* __restrict__ ctrl_trans,
                     const float* __restrict__ ctrl_rots,
                     const float* __restrict__ ctrl_pos,
                     const int*   __restrict__ indices,
                     float* __restrict__ out_means,
                     float* __restrict__ out_quats,
                     int n)
{
    __shared__ float4 s4[K_TOT * EV];

    // ---- build control-point table once per (persistent) block ----
    for (int j = threadIdx.x; j < K_TOT; j += TPB) {
        float4 q = reinterpret_cast<const float4*>(ctrl_rots)[j];
        float nrm = sqrtf(q.x * q.x + q.y * q.y + q.z * q.z + q.w * q.w);
        float inv = 1.0f / fmaxf(nrm, 1e-8f);
        float cw = q.x * inv, cx = q.y * inv, cy = q.z * inv, cz = q.w * inv;

        float px = ctrl_pos[j * 3 + 0];
        float py = ctrl_pos[j * 3 + 1];
        float pz = ctrl_pos[j * 3 + 2];

        float rpx, rpy, rpz;
        quat_rotate(cw, cx, cy, cz, px, py, pz, rpx, rpy, rpz);

        float b0 = px + ctrl_trans[j * 3 + 0] - rpx;
        float b1 = py + ctrl_trans[j * 3 + 1] - rpy;
        float b2 = pz + ctrl_trans[j * 3 + 2] - rpz;

        float4* e = s4 + j * EV;
        e[0] = make_float4(cw, cx, cy, cz);
        e[1] = make_float4(b0, b1, b2, 0.f);
    }
    __syncthreads();

    const int stride = gridDim.x * TPB;

    for (int i = blockIdx.x * TPB + threadIdx.x; i < n; i += stride) {
        // ---- per-gaussian loads ----
        float mx = means[i * 3 + 0];
        float my = means[i * 3 + 1];
        float mz = means[i * 3 + 2];
        float4 gq = reinterpret_cast<const float4*>(quats)[i];   // (w,x,y,z)

        const float2* wp = reinterpret_cast<const float2*>(weights + (size_t)i * K_NB);
        const int2*   ip = reinterpret_cast<const int2*>(indices + (size_t)i * K_NB);

        float am0 = 0.f, am1 = 0.f, am2 = 0.f;
        float aq0 = 0.f, aq1 = 0.f, aq2 = 0.f, aq3 = 0.f;

        #pragma unroll
        for (int kk = 0; kk < K_NB / 2; kk++) {
            float2 tw = wp[kk];
            int2   ti = ip[kk];

            #pragma unroll
            for (int h = 0; h < 2; h++) {
                const float w = (h == 0) ? tw.x : tw.y;
                const int   j = (h == 0) ? ti.x : ti.y;
                const float4* e = s4 + j * EV;
                float4 cq = e[0];
                float4 b  = e[1];

                float vx, vy, vz;
                quat_rotate(cq.x, cq.y, cq.z, cq.w, mx, my, mz, vx, vy, vz);

                am0 = fmaf(w, vx + b.x, am0);
                am1 = fmaf(w, vy + b.y, am1);
                am2 = fmaf(w, vz + b.z, am2);

                aq0 = fmaf(w, cq.x, aq0);
                aq1 = fmaf(w, cq.y, aq1);
                aq2 = fmaf(w, cq.z, aq2);
                aq3 = fmaf(w, cq.w, aq3);
            }
        }

        // normalize blended quaternion (matches reference eps handling)
        float nrm = sqrtf(aq0 * aq0 + aq1 * aq1 + aq2 * aq2 + aq3 * aq3);
        float inv = 1.0f / fmaxf(nrm, 1e-8f);
        float aw = aq0 * inv, ax = aq1 * inv, ay = aq2 * inv, az = aq3 * inv;

        // Hamilton product: blended * gaussian quat  (w,x,y,z)
        float bw = gq.x, bx = gq.y, by = gq.z, bz = gq.w;
        float4 qo;
        qo.x = aw * bw - ax * bx - ay * by - az * bz;
        qo.y = aw * bx + ax * bw + ay * bz - az * by;
        qo.z = aw * by - ax * bz + ay * bw + az * bx;
        qo.w = aw * bz + ax * by - ay * bx + az * bw;

        out_means[i * 3 + 0] = am0;
        out_means[i * 3 + 1] = am1;
        out_means[i * 3 + 2] = am2;
        reinterpret_cast<float4*>(out_quats)[i] = qo;
    }
}

extern "C" void kernel_launch(void* const* d_in, const int* in_sizes, int n_in,
                              void* d_out, int out_size)
{
    const float* means      = (const float*)d_in[0];
    const float* quats      = (const float*)d_in[1];
    const float* weights    = (const float*)d_in[2];
    const float* ctrl_trans = (const float*)d_in[3];
    const float* ctrl_rots  = (const float*)d_in[4];
    const float* ctrl_pos   = (const float*)d_in[5];
    const int*   indices    = (const int*)d_in[6];

    int n = in_sizes[0] / 3;  // means is [N,3]

    float* out_means = (float*)d_out;
    float* out_quats = (float*)d_out + (size_t)n * 3;

    int max_blocks = NUM_SMS * BLKS_PER_SM;
    int need = (n + TPB - 1) / TPB;
    int blocks = need < max_blocks ? need : max_blocks;

    deform4d_kernel<<<blocks, TPB>>>(means, quats, weights,
                                     ctrl_trans, ctrl_rots, ctrl_pos,
                                     indices, out_means, out_quats, n);
}